// round 17
// baseline (speedup 1.0000x reference)
#include <cuda_runtime.h>
#include <cuda_bf16.h>
#include <cstddef>
#include <cstdint>

// Problem constants
#define N_SEQ   64
#define L_SEQ   512
#define D_IN    1280
#define M_ROWS  (N_SEQ * L_SEQ)     // 32768 (n,l) rows
#define N_TILES 8                    // 512 / 64
#define N_PAIRS 36                   // upper-tri tile pairs (lb <= mb)
#define SCALE_CONST 0.08838834764831845f  // 1/(4*sqrt(8))

// Scratch
__device__ float g_h[M_ROWS * 32];          // projected h, [32768][32]
__device__ float g_fo[M_ROWS / 128];        // per-block first-order partials
__device__ float g_partial[N_SEQ * N_PAIRS];// per-tile second-order partials

// ---- packed fp32x2 helpers (K2) ----
__device__ __forceinline__ void fma2(unsigned long long &d,
                                     unsigned long long a,
                                     unsigned long long b) {
    asm("fma.rn.f32x2 %0, %1, %2, %0;" : "+l"(d) : "l"(a), "l"(b));
}
__device__ __forceinline__ float hsum2(unsigned long long u) {
    float lo, hi;
    asm("mov.b64 {%0, %1}, %2;" : "=f"(lo), "=f"(hi) : "l"(u));
    return lo + hi;
}

// ---- warp-MMA helpers (baseline PTX: sm_80+, safe on compute_103) ----
__device__ __forceinline__ uint32_t smem_u32(const void* p) {
    return (uint32_t)__cvta_generic_to_shared(p);
}
#define SWZ(o) ((o) ^ (((o) >> 3) & 0x70))

__device__ __forceinline__ void ldmx4(uint32_t* r, uint32_t a) {
    asm volatile("ldmatrix.sync.aligned.m8n8.x4.shared.b16 {%0,%1,%2,%3}, [%4];"
                 : "=r"(r[0]), "=r"(r[1]), "=r"(r[2]), "=r"(r[3]) : "r"(a));
}
__device__ __forceinline__ void ldmx2(uint32_t* r, uint32_t a) {
    asm volatile("ldmatrix.sync.aligned.m8n8.x2.shared.b16 {%0,%1}, [%2];"
                 : "=r"(r[0]), "=r"(r[1]) : "r"(a));
}
__device__ __forceinline__ void mma16816(float* c, const uint32_t* a,
                                         uint32_t b0, uint32_t b1) {
    asm volatile(
        "mma.sync.aligned.m16n8k16.row.col.f32.bf16.bf16.f32 "
        "{%0,%1,%2,%3}, {%4,%5,%6,%7}, {%8,%9}, {%0,%1,%2,%3};"
        : "+f"(c[0]), "+f"(c[1]), "+f"(c[2]), "+f"(c[3])
        : "r"(a[0]), "r"(a[1]), "r"(a[2]), "r"(a[3]), "r"(b0), "r"(b1));
}

__device__ __forceinline__ void bf16split(float vx, float vy,
                                          uint32_t &hp, uint32_t &lp) {
    __nv_bfloat16 h0 = __float2bfloat16(vx), h1 = __float2bfloat16(vy);
    __nv_bfloat16 l0 = __float2bfloat16(vx - __bfloat162float(h0));
    __nv_bfloat16 l1 = __float2bfloat16(vy - __bfloat162float(h1));
    hp = (uint32_t)__bfloat16_as_ushort(h0) | ((uint32_t)__bfloat16_as_ushort(h1) << 16);
    lp = (uint32_t)__bfloat16_as_ushort(l0) | ((uint32_t)__bfloat16_as_ushort(l1) << 16);
}

// ---------------------------------------------------------------------------
// K1: projection GEMM via mma.sync bf16-split.
// C[128,40] per block (33 real cols), K chunks of 64 fp32 (20 chunks).
// 8 warps: warp w owns m16 band rows 16w..16w+15, all 5 n8 tiles.
// smem tiles (SW128 swizzle, 128B rows): x_hi/x_lo [128][64]bf16,
// w_hi/w_lo [40][64]bf16 (rows 33..39 zero).
// ---------------------------------------------------------------------------
#define K1_THREADS 256
#define TILE_ROWS  128
#define KF         64
#define NCHUNK_K1  (D_IN / KF)        // 20
#define XHI 0
#define XLO 16384
#define WHI 32768
#define WLO 37888                     // 37*1024

__global__ __launch_bounds__(K1_THREADS, 2)
void proj_kernel(const float* __restrict__ x,
                 const float* __restrict__ W_proj,
                 const float* __restrict__ w_token,
                 const float* __restrict__ w_seq) {
    __shared__ __align__(1024) char sm[43008];
    __shared__ float fored[8];

    const int tid  = threadIdx.x;
    const int warp = tid >> 5;      // 0..7 -> m16 band
    const int lane = tid & 31;
    const int rowbase = blockIdx.x * TILE_ROWS;

    // zero W pad rows 33..39 (hi & lo) once
    for (int i = tid; i < 2 * 7 * 32; i += K1_THREADS) {
        int t = i / (7 * 32);
        int j = i - t * (7 * 32);
        *(uint32_t*)(sm + (t ? WLO : WHI) + 33 * 128 + j * 4) = 0u;
    }

    float acc[5][4];
#pragma unroll
    for (int nt = 0; nt < 5; nt++)
#pragma unroll
        for (int q = 0; q < 4; q++) acc[nt][q] = 0.0f;

    // lane-pattern constants for ldmatrix addressing
    const int tl   = lane >> 3;                       // 0..3
    const int arow = (warp << 4) + (lane & 7) + ((tl & 1) << 3);
    const int akb  = (tl >> 1) << 3;                  // 0 or 8 (bf16)
    const int brow4 = (lane & 7) + ((tl >> 1) << 3);  // + n0
    const int bkb4  = (tl & 1) << 3;
    const int brow2 = 32 + (lane & 7);                // 5th ntile
    const int bkb2  = ((lane >> 3) & 1) << 3;

    const uint32_t sb = smem_u32(sm);

    for (int c = 0; c < NCHUNK_K1; c++) {
        const int kb = c * KF;

        // convert x: 128 rows x 32 float2
        for (int p = tid; p < TILE_ROWS * 32; p += K1_THREADS) {
            int row = p >> 5, cp = p & 31;
            float2 v = *(const float2*)(x + (size_t)(rowbase + row) * D_IN + kb + cp * 2);
            uint32_t hp, lp; bf16split(v.x, v.y, hp, lp);
            uint32_t sw = SWZ((uint32_t)(row * 128 + cp * 4));
            *(uint32_t*)(sm + XHI + sw) = hp;
            *(uint32_t*)(sm + XLO + sw) = lp;
        }
        // convert W rows 0..32
        for (int p = tid; p < 33 * 32; p += K1_THREADS) {
            int row = p >> 5, cp = p & 31;
            const float* src = (row < 32) ? (W_proj + (size_t)row * D_IN + kb + cp * 2)
                                          : (w_token + kb + cp * 2);
            float2 v = *(const float2*)src;
            uint32_t hp, lp; bf16split(v.x, v.y, hp, lp);
            uint32_t sw = SWZ((uint32_t)(row * 128 + cp * 4));
            *(uint32_t*)(sm + WHI + sw) = hp;
            *(uint32_t*)(sm + WLO + sw) = lp;
        }
        __syncthreads();

#pragma unroll
        for (int s = 0; s < 4; s++) {
            const int k16 = s * 16;
            uint32_t ahi[4], alo[4];
            uint32_t aoff = SWZ((uint32_t)(arow * 128 + (k16 + akb) * 2));
            ldmx4(ahi, sb + XHI + aoff);
            ldmx4(alo, sb + XLO + aoff);

            uint32_t bh[10], bl[10];
            uint32_t b01 = SWZ((uint32_t)((brow4 + 0)  * 128 + (k16 + bkb4) * 2));
            uint32_t b23 = SWZ((uint32_t)((brow4 + 16) * 128 + (k16 + bkb4) * 2));
            uint32_t b4  = SWZ((uint32_t)(brow2 * 128 + (k16 + bkb2) * 2));
            ldmx4(bh,     sb + WHI + b01);
            ldmx4(bh + 4, sb + WHI + b23);
            ldmx2(bh + 8, sb + WHI + b4);
            ldmx4(bl,     sb + WLO + b01);
            ldmx4(bl + 4, sb + WLO + b23);
            ldmx2(bl + 8, sb + WLO + b4);

#pragma unroll
            for (int nt = 0; nt < 5; nt++) {
                mma16816(acc[nt], ahi, bh[2 * nt], bh[2 * nt + 1]);
                mma16816(acc[nt], alo, bh[2 * nt], bh[2 * nt + 1]);
                mma16816(acc[nt], ahi, bl[2 * nt], bl[2 * nt + 1]);
            }
        }
        __syncthreads();
    }

    // epilogue: stage D into smem [128][40], then coalesced writeout.
    float* st = (float*)sm;
    {
        int g = lane >> 2, t = lane & 3;
        int r0 = (warp << 4) + g;
#pragma unroll
        for (int nt = 0; nt < 5; nt++) {
            int col = nt * 8 + 2 * t;
            st[r0 * 40 + col]           = acc[nt][0];
            st[r0 * 40 + col + 1]       = acc[nt][1];
            st[(r0 + 8) * 40 + col]     = acc[nt][2];
            st[(r0 + 8) * 40 + col + 1] = acc[nt][3];
        }
    }
    __syncthreads();

    for (int i = tid; i < TILE_ROWS * 8; i += K1_THREADS) {
        int r = i >> 3;
        int q = (i & 7) << 2;
        float4 v = make_float4(st[r * 40 + q],     st[r * 40 + q + 1],
                               st[r * 40 + q + 2], st[r * 40 + q + 3]);
        *(float4*)(g_h + (size_t)(rowbase + r) * 32 + q) = v;
    }

    // first-order partial: col 32 = token linear
    {
        const int l0 = rowbase & (L_SEQ - 1);
        float fo = (tid < TILE_ROWS) ? st[tid * 40 + 32] * w_seq[l0 + tid] : 0.0f;
#pragma unroll
        for (int off = 16; off; off >>= 1)
            fo += __shfl_down_sync(0xffffffffu, fo, off);
        if (lane == 0) fored[warp] = fo;
        __syncthreads();
        if (tid == 0) {
            float s = 0.0f;
#pragma unroll
            for (int w = 0; w < 8; w++) s += fored[w];
            g_fo[blockIdx.x] = s;
        }
    }
}

// ---------------------------------------------------------------------------
// K2: second-order (unchanged). G = Hl @ Hm^T per 64x64 tile pair, * priors,
// strict upper mask, deterministic per-block partial.
// ---------------------------------------------------------------------------
#define HPAD 34

__global__ __launch_bounds__(256)
void attn_kernel(const float* __restrict__ priors) {
    __shared__ float hl[64][HPAD];
    __shared__ float hm[64][HPAD];
    __shared__ float red[8];

    const int bx = blockIdx.x;
    const int n  = bx / N_PAIRS;
    const int tp = bx - n * N_PAIRS;

    int lb = 0, rem = tp;
#pragma unroll
    for (int q = 0; q < N_TILES; q++) {
        int cnt = N_TILES - q;
        if (rem < cnt) { lb = q; break; }
        rem -= cnt;
    }
    const int mb = lb + rem;

    const int tid = threadIdx.x;
    const float* Hl = g_h + (size_t)(n * L_SEQ + lb * 64) * 32;
    const float* Hm = g_h + (size_t)(n * L_SEQ + mb * 64) * 32;

    for (int i = tid; i < 512; i += 256) {
        int r  = i >> 3;
        int k4 = (i & 7) << 2;
        float4 v = *(const float4*)(Hl + r * 32 + k4);
        *(float2*)&hl[r][k4]     = make_float2(v.x, v.y);
        *(float2*)&hl[r][k4 + 2] = make_float2(v.z, v.w);
        float4 u = *(const float4*)(Hm + r * 32 + k4);
        *(float2*)&hm[r][k4]     = make_float2(u.x, u.y);
        *(float2*)&hm[r][k4 + 2] = make_float2(u.z, u.w);
    }
    __syncthreads();

    const int lg = tid >> 4;
    const int mg = tid & 15;

    unsigned long long acc[4][4];
#pragma unroll
    for (int i = 0; i < 4; i++)
#pragma unroll
        for (int j = 0; j < 4; j++) acc[i][j] = 0ULL;

#pragma unroll 4
    for (int k2 = 0; k2 < 16; k2++) {
        unsigned long long a[4], b[4];
#pragma unroll
        for (int i = 0; i < 4; i++)
            a[i] = *(const unsigned long long*)&hl[lg + (i << 4)][k2 * 2];
#pragma unroll
        for (int j = 0; j < 4; j++)
            b[j] = *(const unsigned long long*)&hm[mg + (j << 4)][k2 * 2];
#pragma unroll
        for (int i = 0; i < 4; i++)
#pragma unroll
            for (int j = 0; j < 4; j++)
                fma2(acc[i][j], a[i], b[j]);
    }

    float partial = 0.0f;
    const float* P = priors + (size_t)n * L_SEQ * L_SEQ;
#pragma unroll
    for (int i = 0; i < 4; i++) {
        int l = lb * 64 + lg + (i << 4);
#pragma unroll
        for (int j = 0; j < 4; j++) {
            int m = mb * 64 + mg + (j << 4);
            if (m > l)
                partial += hsum2(acc[i][j]) * __ldg(&P[(size_t)l * L_SEQ + m]);
        }
    }

#pragma unroll
    for (int off = 16; off; off >>= 1)
        partial += __shfl_down_sync(0xffffffffu, partial, off);
    if ((tid & 31) == 0) red[tid >> 5] = partial;
    __syncthreads();
    if (tid == 0) {
        float s = 0.0f;
#pragma unroll
        for (int w = 0; w < 8; w++) s += red[w];
        g_partial[bx] = s;
    }
}

// ---------------------------------------------------------------------------
// K3: finalize (unchanged).
// ---------------------------------------------------------------------------
__global__ __launch_bounds__(64)
void final_kernel(const float* __restrict__ b_seq,
                  const float* __restrict__ iscale,
                  float* __restrict__ out) {
    const int n   = blockIdx.x;
    const int tid = threadIdx.x;
    __shared__ float red[2];

    const float sc = SCALE_CONST * iscale[0];
    float s = 0.0f;
    if (tid < 4)       s += g_fo[n * 4 + tid];
    if (tid < N_PAIRS) s += sc * g_partial[n * N_PAIRS + tid];

#pragma unroll
    for (int off = 16; off; off >>= 1)
        s += __shfl_down_sync(0xffffffffu, s, off);
    if ((tid & 31) == 0) red[tid >> 5] = s;
    __syncthreads();
    if (tid == 0) out[n] = red[0] + red[1] + b_seq[0];
}

// ---------------------------------------------------------------------------
extern "C" void kernel_launch(void* const* d_in, const int* in_sizes, int n_in,
                              void* d_out, int out_size) {
    const float* x        = (const float*)d_in[0];  // (64,512,1280)
    const float* priors   = (const float*)d_in[1];  // (64,512,512)
    const float* w_token  = (const float*)d_in[2];  // (1280)
    const float* w_seq    = (const float*)d_in[3];  // (512)
    const float* b_seq    = (const float*)d_in[4];  // scalar
    const float* W_proj   = (const float*)d_in[5];  // (32,1280)
    const float* iscale   = (const float*)d_in[6];  // scalar
    float* out = (float*)d_out;                     // (64)

    proj_kernel<<<M_ROWS / TILE_ROWS, K1_THREADS>>>(x, W_proj, w_token, w_seq);
    attn_kernel<<<N_SEQ * N_PAIRS, 256>>>(priors);
    final_kernel<<<N_SEQ, 64>>>(b_seq, iscale, out);
}